// round 1
// baseline (speedup 1.0000x reference)
#include <cuda_runtime.h>

// JaggedConv2D: per-channel depthwise conv, ragged odd kernel sizes 5..29
// embedded (centered) in a 29x29 window, SAME zero padding.
// B=4, C=128, H=W=256, KMAX=29, fp32 in/out.
//
// Strategy: channels are grouped by their (deterministic) kernel size k.
// Per k a fully-unrolled templated kernel is launched over the contiguous
// channel range. Shared-memory input tile + register-tiled (2x4) compute.

#define BB 4
#define CC 128
#define HH 256
#define WW 256
#define KMAXSZ 29

#define TW 32      // tile width  (outputs)
#define TH 64      // tile height (outputs)
#define RX 4       // outputs per thread in x
#define RY 2       // outputs per thread in y
#define NTH 256    // (TW/RX)*(TH/RY) = 8*32 = 256 threads

template<int K>
__global__ __launch_bounds__(NTH, 2)
void dwconv_k(const float* __restrict__ x,
              const float* __restrict__ kern,
              float* __restrict__ out,
              int ch0, int nch)
{
    constexpr int HALO = K / 2;
    constexpr int IW   = TW + K - 1;            // input tile width
    constexpr int SW   = (IW + 3) & ~3;          // padded smem row stride (16B aligned)
    constexpr int IH   = TH + K - 1;            // input tile height
    constexpr int S    = (KMAXSZ - K) / 2;       // offset of ragged kernel in 29x29 window

    __shared__ float sIn[IH * SW];
    __shared__ float sWt[K * K];

    const int bz = blockIdx.z;
    const int ch = ch0 + (bz % nch);
    const int b  = bz / nch;
    const int tileX0 = blockIdx.x * TW;
    const int tileY0 = blockIdx.y * TH;
    const int tid = threadIdx.x;

    // ---- load ragged kernel window into smem ----
    const float* kbase = kern + (size_t)ch * KMAXSZ * KMAXSZ;
    #pragma unroll 1
    for (int i = tid; i < K * K; i += NTH) {
        int ky = i / K, kx = i % K;
        sWt[i] = kbase[(S + ky) * KMAXSZ + (S + kx)];
    }

    // ---- load input tile (+halo) into smem with zero padding ----
    const float* xbase = x + (size_t)(b * CC + ch) * HH * WW;
    const int inY0 = tileY0 - HALO;
    const int inX0 = tileX0 - HALO;
    #pragma unroll 1
    for (int idx = tid; idx < IH * IW; idx += NTH) {
        int r = idx / IW, c = idx % IW;
        int gy = inY0 + r, gx = inX0 + c;
        float v = 0.0f;
        if (gy >= 0 && gy < HH && gx >= 0 && gx < WW)
            v = xbase[gy * WW + gx];
        sIn[r * SW + c] = v;
    }
    __syncthreads();

    // ---- register-tiled compute: each thread does RY x RX outputs ----
    const int tx = tid & 7;          // 8 threads * RX = 32 cols
    const int ty = tid >> 3;         // 32 threads * RY = 64 rows
    const int r0 = ty * RY;
    const int c0 = tx * RX;

    float acc[RY][RX];
    #pragma unroll
    for (int i = 0; i < RY; i++)
        #pragma unroll
        for (int j = 0; j < RX; j++)
            acc[i][j] = 0.0f;

    #pragma unroll 1
    for (int ky = 0; ky < K; ky++) {
        float wrow[K];
        #pragma unroll
        for (int kx = 0; kx < K; kx++)
            wrow[kx] = sWt[ky * K + kx];

        #pragma unroll
        for (int i = 0; i < RY; i++) {
            const float* rp = &sIn[(r0 + i + ky) * SW + c0];
            float vin[RX + K - 1];
            #pragma unroll
            for (int t = 0; t < RX + K - 1; t++)
                vin[t] = rp[t];
            #pragma unroll
            for (int kx = 0; kx < K; kx++)
                #pragma unroll
                for (int j = 0; j < RX; j++)
                    acc[i][j] = fmaf(wrow[kx], vin[kx + j], acc[i][j]);
        }
    }

    // ---- store (vectorized float4: c0 is 16B aligned, W multiple of 4) ----
    float* obase = out + (size_t)(b * CC + ch) * HH * WW;
    #pragma unroll
    for (int i = 0; i < RY; i++) {
        float4 v;
        v.x = acc[i][0]; v.y = acc[i][1]; v.z = acc[i][2]; v.w = acc[i][3];
        *reinterpret_cast<float4*>(&obase[(size_t)(tileY0 + r0 + i) * WW + tileX0 + c0]) = v;
    }
}

extern "C" void kernel_launch(void* const* d_in, const int* in_sizes, int n_in,
                              void* d_out, int out_size)
{
    (void)in_sizes; (void)n_in; (void)out_size;
    const float* x    = (const float*)d_in[0];
    const float* kern = (const float*)d_in[1];
    float* out        = (float*)d_out;

    // Per-channel kernel sizes: np.linspace(5,29,128).astype(int64), forced odd.
    // Exact fractional values are m/127 away from integers -> truncation is safe.
    int ksz[CC];
    for (int i = 0; i < CC; i++) {
        int k = (int)(5.0 + 24.0 * (double)i / 127.0);
        if ((k & 1) == 0) k -= 1;
        ksz[i] = k;
    }

    dim3 block(NTH, 1, 1);
    int i = 0;
    while (i < CC) {
        int k = ksz[i];
        int j = i;
        while (j < CC && ksz[j] == k) j++;
        int nch = j - i;
        dim3 grid(WW / TW, HH / TH, BB * nch);
        switch (k) {
            case  5: dwconv_k< 5><<<grid, block>>>(x, kern, out, i, nch); break;
            case  7: dwconv_k< 7><<<grid, block>>>(x, kern, out, i, nch); break;
            case  9: dwconv_k< 9><<<grid, block>>>(x, kern, out, i, nch); break;
            case 11: dwconv_k<11><<<grid, block>>>(x, kern, out, i, nch); break;
            case 13: dwconv_k<13><<<grid, block>>>(x, kern, out, i, nch); break;
            case 15: dwconv_k<15><<<grid, block>>>(x, kern, out, i, nch); break;
            case 17: dwconv_k<17><<<grid, block>>>(x, kern, out, i, nch); break;
            case 19: dwconv_k<19><<<grid, block>>>(x, kern, out, i, nch); break;
            case 21: dwconv_k<21><<<grid, block>>>(x, kern, out, i, nch); break;
            case 23: dwconv_k<23><<<grid, block>>>(x, kern, out, i, nch); break;
            case 25: dwconv_k<25><<<grid, block>>>(x, kern, out, i, nch); break;
            case 27: dwconv_k<27><<<grid, block>>>(x, kern, out, i, nch); break;
            case 29: dwconv_k<29><<<grid, block>>>(x, kern, out, i, nch); break;
            default: break; // cannot happen
        }
        i = j;
    }
}

// round 2
// speedup vs baseline: 1.5666x; 1.5666x over previous
#include <cuda_runtime.h>

// JaggedConv2D: per-channel depthwise conv, ragged odd kernels 5..29 centered
// in 29x29 window, SAME padding. B=4, C=128, H=W=256, fp32.
//
// R2: single fused launch; 64x128 output tiles; RX=8 x RY=4 register tile;
// vectorized LDS.128 input reads (conflict-free); descending-K schedule.

#define BB 4
#define CC 128
#define HH 256
#define WW 256
#define KMAXSZ 29

#define TW 64
#define TH 128
#define RX 8
#define RY 4
#define NTH 256

#define WT_OFF 848   // floats; 29*29=841 rounded up, 16B aligned

template<int K>
__device__ __forceinline__ void conv_body(const float* __restrict__ x,
                                          const float* __restrict__ kern,
                                          float* __restrict__ out,
                                          int ch, int b, float* smem)
{
    constexpr int HALO = K / 2;
    constexpr int IW   = TW + K - 1;
    constexpr int IH   = TH + K - 1;
    constexpr int NV   = (K + 10) / 4;              // float4 loads per vin row
    constexpr int REACH = (TW - RX) + 4 * NV;       // max col read by compute
    constexpr int SW_RAW = (IW > REACH) ? IW : REACH;
    constexpr int SW   = (SW_RAW + 3) & ~3;
    constexpr int S    = (KMAXSZ - K) / 2;

    float* sWt = smem;
    float* sIn = smem + WT_OFF;

    const int tid = threadIdx.x;
    const int tileX0 = blockIdx.x * TW;
    const int tileY0 = blockIdx.y * TH;

    // ---- weights: ragged KxK window of the 29x29 kernel ----
    const float* kbase = kern + (size_t)ch * KMAXSZ * KMAXSZ;
    #pragma unroll 1
    for (int i = tid; i < K * K; i += NTH) {
        int ky = i / K, kx = i % K;
        sWt[i] = kbase[(S + ky) * KMAXSZ + (S + kx)];
    }

    // ---- input tile (+halo) into smem, zero-padded (incl. SW padding cols) ----
    const float* xbase = x + (size_t)(b * CC + ch) * HH * WW;
    const int inY0 = tileY0 - HALO;
    const int inX0 = tileX0 - HALO;
    #pragma unroll 1
    for (int idx = tid; idx < IH * SW; idx += NTH) {
        int r = idx / SW, c = idx - r * SW;
        int gy = inY0 + r, gx = inX0 + c;
        float v = 0.0f;
        if (c < IW && gy >= 0 && gy < HH && gx >= 0 && gx < WW)
            v = xbase[gy * WW + gx];
        sIn[idx] = v;
    }
    __syncthreads();

    // ---- compute: 8 threads x (RX=8 cols), 32 threads y (RY=4 rows) ----
    const int tx = tid & 7;
    const int ty = tid >> 3;
    const int c0 = tx * RX;          // 32B aligned
    const int r0 = ty * RY;

    float acc[RY][RX];
    #pragma unroll
    for (int i = 0; i < RY; i++)
        #pragma unroll
        for (int j = 0; j < RX; j++)
            acc[i][j] = 0.0f;

    #pragma unroll 1
    for (int ky = 0; ky < K; ky++) {
        float wrow[K];
        #pragma unroll
        for (int kx = 0; kx < K; kx++)
            wrow[kx] = sWt[ky * K + kx];

        #pragma unroll
        for (int i = 0; i < RY; i++) {
            const float* rp = &sIn[(r0 + i + ky) * SW + c0];
            float vin[NV * 4];
            #pragma unroll
            for (int t = 0; t < NV; t++) {
                float4 q = *reinterpret_cast<const float4*>(rp + 4 * t);
                vin[4 * t + 0] = q.x; vin[4 * t + 1] = q.y;
                vin[4 * t + 2] = q.z; vin[4 * t + 3] = q.w;
            }
            #pragma unroll
            for (int kx = 0; kx < K; kx++)
                #pragma unroll
                for (int j = 0; j < RX; j++)
                    acc[i][j] = fmaf(wrow[kx], vin[kx + j], acc[i][j]);
        }
    }

    // ---- store: two float4 per row per thread ----
    float* obase = out + (size_t)(b * CC + ch) * HH * WW;
    #pragma unroll
    for (int i = 0; i < RY; i++) {
        float* op = &obase[(size_t)(tileY0 + r0 + i) * WW + tileX0 + c0];
        float4 v0, v1;
        v0.x = acc[i][0]; v0.y = acc[i][1]; v0.z = acc[i][2]; v0.w = acc[i][3];
        v1.x = acc[i][4]; v1.y = acc[i][5]; v1.z = acc[i][6]; v1.w = acc[i][7];
        *reinterpret_cast<float4*>(op)     = v0;
        *reinterpret_cast<float4*>(op + 4) = v1;
    }
}

__global__ __launch_bounds__(NTH, 2)
void jagged_conv(const float* __restrict__ x,
                 const float* __restrict__ kern,
                 float* __restrict__ out)
{
    extern __shared__ float smem[];
    const int z  = blockIdx.z;
    const int ch = (CC - 1) - (z >> 2);   // descending K: big kernels first
    const int b  = z & 3;

    // k_i = floor(5 + 24*i/127), forced odd (matches np.linspace/astype)
    int k = 5 + (24 * ch) / 127;
    if ((k & 1) == 0) k -= 1;

    switch (k) {
        case  5: conv_body< 5>(x, kern, out, ch, b, smem); break;
        case  7: conv_body< 7>(x, kern, out, ch, b, smem); break;
        case  9: conv_body< 9>(x, kern, out, ch, b, smem); break;
        case 11: conv_body<11>(x, kern, out, ch, b, smem); break;
        case 13: conv_body<13>(x, kern, out, ch, b, smem); break;
        case 15: conv_body<15>(x, kern, out, ch, b, smem); break;
        case 17: conv_body<17>(x, kern, out, ch, b, smem); break;
        case 19: conv_body<19>(x, kern, out, ch, b, smem); break;
        case 21: conv_body<21>(x, kern, out, ch, b, smem); break;
        case 23: conv_body<23>(x, kern, out, ch, b, smem); break;
        case 25: conv_body<25>(x, kern, out, ch, b, smem); break;
        case 27: conv_body<27>(x, kern, out, ch, b, smem); break;
        case 29: conv_body<29>(x, kern, out, ch, b, smem); break;
        default: break;
    }
}

extern "C" void kernel_launch(void* const* d_in, const int* in_sizes, int n_in,
                              void* d_out, int out_size)
{
    (void)in_sizes; (void)n_in; (void)out_size;
    const float* x    = (const float*)d_in[0];
    const float* kern = (const float*)d_in[1];
    float* out        = (float*)d_out;

    // smem for K=29: WT_OFF + (TH+28)*(SW=92) floats
    const int smem_bytes = (WT_OFF + (TH + 28) * 92) * (int)sizeof(float);
    cudaFuncSetAttribute(jagged_conv,
                         cudaFuncAttributeMaxDynamicSharedMemorySize, smem_bytes);

    dim3 grid(WW / TW, HH / TH, BB * CC);
    dim3 block(NTH, 1, 1);
    jagged_conv<<<grid, block, smem_bytes>>>(x, kern, out);
}

// round 3
// speedup vs baseline: 1.5833x; 1.0107x over previous
#include <cuda_runtime.h>

// JaggedConv2D: per-channel depthwise conv, ragged odd kernels 5..29 centered
// in 29x29 window, SAME padding. B=4, C=128, H=W=256, fp32.
//
// R2: single fused launch; 64x128 output tiles; RX=8 x RY=4 register tile;
// vectorized LDS.128 input reads (conflict-free); descending-K schedule.

#define BB 4
#define CC 128
#define HH 256
#define WW 256
#define KMAXSZ 29

#define TW 64
#define TH 128
#define RX 8
#define RY 4
#define NTH 256

#define WT_OFF 848   // floats; 29*29=841 rounded up, 16B aligned

template<int K>
__device__ __forceinline__ void conv_body(const float* __restrict__ x,
                                          const float* __restrict__ kern,
                                          float* __restrict__ out,
                                          int ch, int b, float* smem)
{
    constexpr int HALO = K / 2;
    constexpr int IW   = TW + K - 1;
    constexpr int IH   = TH + K - 1;
    constexpr int NV   = (K + 10) / 4;              // float4 loads per vin row
    constexpr int REACH = (TW - RX) + 4 * NV;       // max col read by compute
    constexpr int SW_RAW = (IW > REACH) ? IW : REACH;
    constexpr int SW   = (SW_RAW + 3) & ~3;
    constexpr int S    = (KMAXSZ - K) / 2;

    float* sWt = smem;
    float* sIn = smem + WT_OFF;

    const int tid = threadIdx.x;
    const int tileX0 = blockIdx.x * TW;
    const int tileY0 = blockIdx.y * TH;

    // ---- weights: ragged KxK window of the 29x29 kernel ----
    const float* kbase = kern + (size_t)ch * KMAXSZ * KMAXSZ;
    #pragma unroll 1
    for (int i = tid; i < K * K; i += NTH) {
        int ky = i / K, kx = i % K;
        sWt[i] = kbase[(S + ky) * KMAXSZ + (S + kx)];
    }

    // ---- input tile (+halo) into smem, zero-padded (incl. SW padding cols) ----
    const float* xbase = x + (size_t)(b * CC + ch) * HH * WW;
    const int inY0 = tileY0 - HALO;
    const int inX0 = tileX0 - HALO;
    #pragma unroll 1
    for (int idx = tid; idx < IH * SW; idx += NTH) {
        int r = idx / SW, c = idx - r * SW;
        int gy = inY0 + r, gx = inX0 + c;
        float v = 0.0f;
        if (c < IW && gy >= 0 && gy < HH && gx >= 0 && gx < WW)
            v = xbase[gy * WW + gx];
        sIn[idx] = v;
    }
    __syncthreads();

    // ---- compute: 8 threads x (RX=8 cols), 32 threads y (RY=4 rows) ----
    const int tx = tid & 7;
    const int ty = tid >> 3;
    const int c0 = tx * RX;          // 32B aligned
    const int r0 = ty * RY;

    float acc[RY][RX];
    #pragma unroll
    for (int i = 0; i < RY; i++)
        #pragma unroll
        for (int j = 0; j < RX; j++)
            acc[i][j] = 0.0f;

    #pragma unroll 1
    for (int ky = 0; ky < K; ky++) {
        float wrow[K];
        #pragma unroll
        for (int kx = 0; kx < K; kx++)
            wrow[kx] = sWt[ky * K + kx];

        #pragma unroll
        for (int i = 0; i < RY; i++) {
            const float* rp = &sIn[(r0 + i + ky) * SW + c0];
            float vin[NV * 4];
            #pragma unroll
            for (int t = 0; t < NV; t++) {
                float4 q = *reinterpret_cast<const float4*>(rp + 4 * t);
                vin[4 * t + 0] = q.x; vin[4 * t + 1] = q.y;
                vin[4 * t + 2] = q.z; vin[4 * t + 3] = q.w;
            }
            #pragma unroll
            for (int kx = 0; kx < K; kx++)
                #pragma unroll
                for (int j = 0; j < RX; j++)
                    acc[i][j] = fmaf(wrow[kx], vin[kx + j], acc[i][j]);
        }
    }

    // ---- store: two float4 per row per thread ----
    float* obase = out + (size_t)(b * CC + ch) * HH * WW;
    #pragma unroll
    for (int i = 0; i < RY; i++) {
        float* op = &obase[(size_t)(tileY0 + r0 + i) * WW + tileX0 + c0];
        float4 v0, v1;
        v0.x = acc[i][0]; v0.y = acc[i][1]; v0.z = acc[i][2]; v0.w = acc[i][3];
        v1.x = acc[i][4]; v1.y = acc[i][5]; v1.z = acc[i][6]; v1.w = acc[i][7];
        *reinterpret_cast<float4*>(op)     = v0;
        *reinterpret_cast<float4*>(op + 4) = v1;
    }
}

__global__ __launch_bounds__(NTH, 2)
void jagged_conv(const float* __restrict__ x,
                 const float* __restrict__ kern,
                 float* __restrict__ out)
{
    extern __shared__ float smem[];
    const int z  = blockIdx.z;
    const int ch = (CC - 1) - (z >> 2);   // descending K: big kernels first
    const int b  = z & 3;

    // k_i = floor(5 + 24*i/127), forced odd (matches np.linspace/astype)
    int k = 5 + (24 * ch) / 127;
    if ((k & 1) == 0) k -= 1;

    switch (k) {
        case  5: conv_body< 5>(x, kern, out, ch, b, smem); break;
        case  7: conv_body< 7>(x, kern, out, ch, b, smem); break;
        case  9: conv_body< 9>(x, kern, out, ch, b, smem); break;
        case 11: conv_body<11>(x, kern, out, ch, b, smem); break;
        case 13: conv_body<13>(x, kern, out, ch, b, smem); break;
        case 15: conv_body<15>(x, kern, out, ch, b, smem); break;
        case 17: conv_body<17>(x, kern, out, ch, b, smem); break;
        case 19: conv_body<19>(x, kern, out, ch, b, smem); break;
        case 21: conv_body<21>(x, kern, out, ch, b, smem); break;
        case 23: conv_body<23>(x, kern, out, ch, b, smem); break;
        case 25: conv_body<25>(x, kern, out, ch, b, smem); break;
        case 27: conv_body<27>(x, kern, out, ch, b, smem); break;
        case 29: conv_body<29>(x, kern, out, ch, b, smem); break;
        default: break;
    }
}

extern "C" void kernel_launch(void* const* d_in, const int* in_sizes, int n_in,
                              void* d_out, int out_size)
{
    (void)in_sizes; (void)n_in; (void)out_size;
    const float* x    = (const float*)d_in[0];
    const float* kern = (const float*)d_in[1];
    float* out        = (float*)d_out;

    // smem for K=29: WT_OFF + (TH+28)*(SW=92) floats
    const int smem_bytes = (WT_OFF + (TH + 28) * 92) * (int)sizeof(float);
    cudaFuncSetAttribute(jagged_conv,
                         cudaFuncAttributeMaxDynamicSharedMemorySize, smem_bytes);

    dim3 grid(WW / TW, HH / TH, BB * CC);
    dim3 block(NTH, 1, 1);
    jagged_conv<<<grid, block, smem_bytes>>>(x, kern, out);
}

// round 4
// speedup vs baseline: 1.5842x; 1.0006x over previous
#include <cuda_runtime.h>

// JaggedConv2D: per-channel depthwise conv, ragged odd kernels 5..29 centered
// in 29x29 window, SAME padding. B=4, C=128, H=W=256, fp32.
//
// R2: single fused launch; 64x128 output tiles; RX=8 x RY=4 register tile;
// vectorized LDS.128 input reads (conflict-free); descending-K schedule.

#define BB 4
#define CC 128
#define HH 256
#define WW 256
#define KMAXSZ 29

#define TW 64
#define TH 128
#define RX 8
#define RY 4
#define NTH 256

#define WT_OFF 848   // floats; 29*29=841 rounded up, 16B aligned

template<int K>
__device__ __forceinline__ void conv_body(const float* __restrict__ x,
                                          const float* __restrict__ kern,
                                          float* __restrict__ out,
                                          int ch, int b, float* smem)
{
    constexpr int HALO = K / 2;
    constexpr int IW   = TW + K - 1;
    constexpr int IH   = TH + K - 1;
    constexpr int NV   = (K + 10) / 4;              // float4 loads per vin row
    constexpr int REACH = (TW - RX) + 4 * NV;       // max col read by compute
    constexpr int SW_RAW = (IW > REACH) ? IW : REACH;
    constexpr int SW   = (SW_RAW + 3) & ~3;
    constexpr int S    = (KMAXSZ - K) / 2;

    float* sWt = smem;
    float* sIn = smem + WT_OFF;

    const int tid = threadIdx.x;
    const int tileX0 = blockIdx.x * TW;
    const int tileY0 = blockIdx.y * TH;

    // ---- weights: ragged KxK window of the 29x29 kernel ----
    const float* kbase = kern + (size_t)ch * KMAXSZ * KMAXSZ;
    #pragma unroll 1
    for (int i = tid; i < K * K; i += NTH) {
        int ky = i / K, kx = i % K;
        sWt[i] = kbase[(S + ky) * KMAXSZ + (S + kx)];
    }

    // ---- input tile (+halo) into smem, zero-padded (incl. SW padding cols) ----
    const float* xbase = x + (size_t)(b * CC + ch) * HH * WW;
    const int inY0 = tileY0 - HALO;
    const int inX0 = tileX0 - HALO;
    #pragma unroll 1
    for (int idx = tid; idx < IH * SW; idx += NTH) {
        int r = idx / SW, c = idx - r * SW;
        int gy = inY0 + r, gx = inX0 + c;
        float v = 0.0f;
        if (c < IW && gy >= 0 && gy < HH && gx >= 0 && gx < WW)
            v = xbase[gy * WW + gx];
        sIn[idx] = v;
    }
    __syncthreads();

    // ---- compute: 8 threads x (RX=8 cols), 32 threads y (RY=4 rows) ----
    const int tx = tid & 7;
    const int ty = tid >> 3;
    const int c0 = tx * RX;          // 32B aligned
    const int r0 = ty * RY;

    float acc[RY][RX];
    #pragma unroll
    for (int i = 0; i < RY; i++)
        #pragma unroll
        for (int j = 0; j < RX; j++)
            acc[i][j] = 0.0f;

    #pragma unroll 1
    for (int ky = 0; ky < K; ky++) {
        float wrow[K];
        #pragma unroll
        for (int kx = 0; kx < K; kx++)
            wrow[kx] = sWt[ky * K + kx];

        #pragma unroll
        for (int i = 0; i < RY; i++) {
            const float* rp = &sIn[(r0 + i + ky) * SW + c0];
            float vin[NV * 4];
            #pragma unroll
            for (int t = 0; t < NV; t++) {
                float4 q = *reinterpret_cast<const float4*>(rp + 4 * t);
                vin[4 * t + 0] = q.x; vin[4 * t + 1] = q.y;
                vin[4 * t + 2] = q.z; vin[4 * t + 3] = q.w;
            }
            #pragma unroll
            for (int kx = 0; kx < K; kx++)
                #pragma unroll
                for (int j = 0; j < RX; j++)
                    acc[i][j] = fmaf(wrow[kx], vin[kx + j], acc[i][j]);
        }
    }

    // ---- store: two float4 per row per thread ----
    float* obase = out + (size_t)(b * CC + ch) * HH * WW;
    #pragma unroll
    for (int i = 0; i < RY; i++) {
        float* op = &obase[(size_t)(tileY0 + r0 + i) * WW + tileX0 + c0];
        float4 v0, v1;
        v0.x = acc[i][0]; v0.y = acc[i][1]; v0.z = acc[i][2]; v0.w = acc[i][3];
        v1.x = acc[i][4]; v1.y = acc[i][5]; v1.z = acc[i][6]; v1.w = acc[i][7];
        *reinterpret_cast<float4*>(op)     = v0;
        *reinterpret_cast<float4*>(op + 4) = v1;
    }
}

__global__ __launch_bounds__(NTH, 2)
void jagged_conv(const float* __restrict__ x,
                 const float* __restrict__ kern,
                 float* __restrict__ out)
{
    extern __shared__ float smem[];
    const int z  = blockIdx.z;
    const int ch = (CC - 1) - (z >> 2);   // descending K: big kernels first
    const int b  = z & 3;

    // k_i = floor(5 + 24*i/127), forced odd (matches np.linspace/astype)
    int k = 5 + (24 * ch) / 127;
    if ((k & 1) == 0) k -= 1;

    switch (k) {
        case  5: conv_body< 5>(x, kern, out, ch, b, smem); break;
        case  7: conv_body< 7>(x, kern, out, ch, b, smem); break;
        case  9: conv_body< 9>(x, kern, out, ch, b, smem); break;
        case 11: conv_body<11>(x, kern, out, ch, b, smem); break;
        case 13: conv_body<13>(x, kern, out, ch, b, smem); break;
        case 15: conv_body<15>(x, kern, out, ch, b, smem); break;
        case 17: conv_body<17>(x, kern, out, ch, b, smem); break;
        case 19: conv_body<19>(x, kern, out, ch, b, smem); break;
        case 21: conv_body<21>(x, kern, out, ch, b, smem); break;
        case 23: conv_body<23>(x, kern, out, ch, b, smem); break;
        case 25: conv_body<25>(x, kern, out, ch, b, smem); break;
        case 27: conv_body<27>(x, kern, out, ch, b, smem); break;
        case 29: conv_body<29>(x, kern, out, ch, b, smem); break;
        default: break;
    }
}

extern "C" void kernel_launch(void* const* d_in, const int* in_sizes, int n_in,
                              void* d_out, int out_size)
{
    (void)in_sizes; (void)n_in; (void)out_size;
    const float* x    = (const float*)d_in[0];
    const float* kern = (const float*)d_in[1];
    float* out        = (float*)d_out;

    // smem for K=29: WT_OFF + (TH+28)*(SW=92) floats
    const int smem_bytes = (WT_OFF + (TH + 28) * 92) * (int)sizeof(float);
    cudaFuncSetAttribute(jagged_conv,
                         cudaFuncAttributeMaxDynamicSharedMemorySize, smem_bytes);

    dim3 grid(WW / TW, HH / TH, BB * CC);
    dim3 block(NTH, 1, 1);
    jagged_conv<<<grid, block, smem_bytes>>>(x, kern, out);
}

// round 5
// speedup vs baseline: 1.6188x; 1.0218x over previous
#include <cuda_runtime.h>

// JaggedConv2D: per-channel depthwise conv, ragged odd kernels 5..29 centered
// in 29x29 window, SAME padding. B=4, C=128, H=W=256, fp32.
//
// R5: conflict-free LDS.128 via parity-pair lane mapping.
//   lanes: parity=tid&1, tx=(tid>>1)&7, rg=tid>>4
//   thread computes rows {rg*8+parity+2k, k=0..3} x cols [8*tx, 8*tx+8)
//   smem row stride SW forced to SW/4 odd -> each quarter-warp's 8x16B LDS.128
//   chunks cover 8 distinct bank groups -> 4-wavefront (minimum) per LDS.128.

#define BB 4
#define CC 128
#define HH 256
#define WW 256
#define KMAXSZ 29

#define TW 64
#define TH 128
#define RX 8
#define RY 4
#define NTH 256

#define WT_OFF 848   // floats; 29*29=841 rounded up, 16B aligned

template<int K>
__device__ __forceinline__ void conv_body(const float* __restrict__ x,
                                          const float* __restrict__ kern,
                                          float* __restrict__ out,
                                          int ch, int b, float* smem)
{
    constexpr int HALO = K / 2;
    constexpr int IW   = TW + K - 1;
    constexpr int IH   = TH + K - 1;
    constexpr int NV   = (K + 10) / 4;              // float4 loads per vin row
    constexpr int REACH = (TW - RX) + 4 * NV;       // max col read by compute
    constexpr int SW0 = (((IW > REACH) ? IW : REACH) + 3) & ~3;
    constexpr int SW  = ((SW0 >> 2) & 1) ? SW0 : SW0 + 4;  // force SW/4 odd
    constexpr int S    = (KMAXSZ - K) / 2;

    float* sWt = smem;
    float* sIn = smem + WT_OFF;

    const int tid = threadIdx.x;
    const int tileX0 = blockIdx.x * TW;
    const int tileY0 = blockIdx.y * TH;

    // ---- weights: ragged KxK window of the 29x29 kernel ----
    const float* kbase = kern + (size_t)ch * KMAXSZ * KMAXSZ;
    #pragma unroll 1
    for (int i = tid; i < K * K; i += NTH) {
        int ky = i / K, kx = i % K;
        sWt[i] = kbase[(S + ky) * KMAXSZ + (S + kx)];
    }

    // ---- input tile (+halo) into smem, zero-padded (incl. SW padding cols) ----
    const float* xbase = x + (size_t)(b * CC + ch) * HH * WW;
    const int inY0 = tileY0 - HALO;
    const int inX0 = tileX0 - HALO;
    #pragma unroll 1
    for (int idx = tid; idx < IH * SW; idx += NTH) {
        int r = idx / SW, c = idx - r * SW;
        int gy = inY0 + r, gx = inX0 + c;
        float v = 0.0f;
        if (c < IW && gy >= 0 && gy < HH && gx >= 0 && gx < WW)
            v = xbase[gy * WW + gx];
        sIn[idx] = v;
    }
    __syncthreads();

    // ---- conflict-free lane mapping ----
    const int parity = tid & 1;
    const int tx     = (tid >> 1) & 7;
    const int rg     = tid >> 4;             // 0..15
    const int c0 = tx * RX;                  // 32B aligned
    const int r0 = rg * 8 + parity;          // rows r0 + 2k, k=0..RY-1

    float acc[RY][RX];
    #pragma unroll
    for (int i = 0; i < RY; i++)
        #pragma unroll
        for (int j = 0; j < RX; j++)
            acc[i][j] = 0.0f;

    #pragma unroll 1
    for (int ky = 0; ky < K; ky++) {
        float wrow[K];
        #pragma unroll
        for (int kx = 0; kx < K; kx++)
            wrow[kx] = sWt[ky * K + kx];

        #pragma unroll
        for (int i = 0; i < RY; i++) {
            const float* rp = &sIn[(r0 + 2 * i + ky) * SW + c0];
            float vin[NV * 4];
            #pragma unroll
            for (int t = 0; t < NV; t++) {
                float4 q = *reinterpret_cast<const float4*>(rp + 4 * t);
                vin[4 * t + 0] = q.x; vin[4 * t + 1] = q.y;
                vin[4 * t + 2] = q.z; vin[4 * t + 3] = q.w;
            }
            #pragma unroll
            for (int kx = 0; kx < K; kx++)
                #pragma unroll
                for (int j = 0; j < RX; j++)
                    acc[i][j] = fmaf(wrow[kx], vin[kx + j], acc[i][j]);
        }
    }

    // ---- store: two float4 per row per thread ----
    float* obase = out + (size_t)(b * CC + ch) * HH * WW;
    #pragma unroll
    for (int i = 0; i < RY; i++) {
        float* op = &obase[(size_t)(tileY0 + r0 + 2 * i) * WW + tileX0 + c0];
        float4 v0, v1;
        v0.x = acc[i][0]; v0.y = acc[i][1]; v0.z = acc[i][2]; v0.w = acc[i][3];
        v1.x = acc[i][4]; v1.y = acc[i][5]; v1.z = acc[i][6]; v1.w = acc[i][7];
        *reinterpret_cast<float4*>(op)     = v0;
        *reinterpret_cast<float4*>(op + 4) = v1;
    }
}

__global__ __launch_bounds__(NTH, 2)
void jagged_conv(const float* __restrict__ x,
                 const float* __restrict__ kern,
                 float* __restrict__ out)
{
    extern __shared__ float smem[];
    const int z  = blockIdx.z;
    const int ch = (CC - 1) - (z >> 2);   // descending K: big kernels first
    const int b  = z & 3;

    // k_i = floor(5 + 24*i/127), forced odd (matches np.linspace/astype)
    int k = 5 + (24 * ch) / 127;
    if ((k & 1) == 0) k -= 1;

    switch (k) {
        case  5: conv_body< 5>(x, kern, out, ch, b, smem); break;
        case  7: conv_body< 7>(x, kern, out, ch, b, smem); break;
        case  9: conv_body< 9>(x, kern, out, ch, b, smem); break;
        case 11: conv_body<11>(x, kern, out, ch, b, smem); break;
        case 13: conv_body<13>(x, kern, out, ch, b, smem); break;
        case 15: conv_body<15>(x, kern, out, ch, b, smem); break;
        case 17: conv_body<17>(x, kern, out, ch, b, smem); break;
        case 19: conv_body<19>(x, kern, out, ch, b, smem); break;
        case 21: conv_body<21>(x, kern, out, ch, b, smem); break;
        case 23: conv_body<23>(x, kern, out, ch, b, smem); break;
        case 25: conv_body<25>(x, kern, out, ch, b, smem); break;
        case 27: conv_body<27>(x, kern, out, ch, b, smem); break;
        case 29: conv_body<29>(x, kern, out, ch, b, smem); break;
        default: break;
    }
}

extern "C" void kernel_launch(void* const* d_in, const int* in_sizes, int n_in,
                              void* d_out, int out_size)
{
    (void)in_sizes; (void)n_in; (void)out_size;
    const float* x    = (const float*)d_in[0];
    const float* kern = (const float*)d_in[1];
    float* out        = (float*)d_out;

    // smem sized for K=29: WT_OFF + (TH+28) * SW(29)=92 floats
    const int smem_bytes = (WT_OFF + (TH + 28) * 92) * (int)sizeof(float);
    cudaFuncSetAttribute(jagged_conv,
                         cudaFuncAttributeMaxDynamicSharedMemorySize, smem_bytes);

    dim3 grid(WW / TW, HH / TH, BB * CC);
    dim3 block(NTH, 1, 1);
    jagged_conv<<<grid, block, smem_bytes>>>(x, kern, out);
}

// round 6
// speedup vs baseline: 1.6213x; 1.0015x over previous
#include <cuda_runtime.h>

// JaggedConv2D: per-channel depthwise conv, ragged odd kernels 5..29 centered
// in 29x29 window, SAME padding. B=4, C=128, H=W=256, fp32.
//
// R5: conflict-free LDS.128 via parity-pair lane mapping.
//   lanes: parity=tid&1, tx=(tid>>1)&7, rg=tid>>4
//   thread computes rows {rg*8+parity+2k, k=0..3} x cols [8*tx, 8*tx+8)
//   smem row stride SW forced to SW/4 odd -> each quarter-warp's 8x16B LDS.128
//   chunks cover 8 distinct bank groups -> 4-wavefront (minimum) per LDS.128.

#define BB 4
#define CC 128
#define HH 256
#define WW 256
#define KMAXSZ 29

#define TW 64
#define TH 128
#define RX 8
#define RY 4
#define NTH 256

#define WT_OFF 848   // floats; 29*29=841 rounded up, 16B aligned

template<int K>
__device__ __forceinline__ void conv_body(const float* __restrict__ x,
                                          const float* __restrict__ kern,
                                          float* __restrict__ out,
                                          int ch, int b, float* smem)
{
    constexpr int HALO = K / 2;
    constexpr int IW   = TW + K - 1;
    constexpr int IH   = TH + K - 1;
    constexpr int NV   = (K + 10) / 4;              // float4 loads per vin row
    constexpr int REACH = (TW - RX) + 4 * NV;       // max col read by compute
    constexpr int SW0 = (((IW > REACH) ? IW : REACH) + 3) & ~3;
    constexpr int SW  = ((SW0 >> 2) & 1) ? SW0 : SW0 + 4;  // force SW/4 odd
    constexpr int S    = (KMAXSZ - K) / 2;

    float* sWt = smem;
    float* sIn = smem + WT_OFF;

    const int tid = threadIdx.x;
    const int tileX0 = blockIdx.x * TW;
    const int tileY0 = blockIdx.y * TH;

    // ---- weights: ragged KxK window of the 29x29 kernel ----
    const float* kbase = kern + (size_t)ch * KMAXSZ * KMAXSZ;
    #pragma unroll 1
    for (int i = tid; i < K * K; i += NTH) {
        int ky = i / K, kx = i % K;
        sWt[i] = kbase[(S + ky) * KMAXSZ + (S + kx)];
    }

    // ---- input tile (+halo) into smem, zero-padded (incl. SW padding cols) ----
    const float* xbase = x + (size_t)(b * CC + ch) * HH * WW;
    const int inY0 = tileY0 - HALO;
    const int inX0 = tileX0 - HALO;
    #pragma unroll 1
    for (int idx = tid; idx < IH * SW; idx += NTH) {
        int r = idx / SW, c = idx - r * SW;
        int gy = inY0 + r, gx = inX0 + c;
        float v = 0.0f;
        if (c < IW && gy >= 0 && gy < HH && gx >= 0 && gx < WW)
            v = xbase[gy * WW + gx];
        sIn[idx] = v;
    }
    __syncthreads();

    // ---- conflict-free lane mapping ----
    const int parity = tid & 1;
    const int tx     = (tid >> 1) & 7;
    const int rg     = tid >> 4;             // 0..15
    const int c0 = tx * RX;                  // 32B aligned
    const int r0 = rg * 8 + parity;          // rows r0 + 2k, k=0..RY-1

    float acc[RY][RX];
    #pragma unroll
    for (int i = 0; i < RY; i++)
        #pragma unroll
        for (int j = 0; j < RX; j++)
            acc[i][j] = 0.0f;

    #pragma unroll 1
    for (int ky = 0; ky < K; ky++) {
        float wrow[K];
        #pragma unroll
        for (int kx = 0; kx < K; kx++)
            wrow[kx] = sWt[ky * K + kx];

        #pragma unroll
        for (int i = 0; i < RY; i++) {
            const float* rp = &sIn[(r0 + 2 * i + ky) * SW + c0];
            float vin[NV * 4];
            #pragma unroll
            for (int t = 0; t < NV; t++) {
                float4 q = *reinterpret_cast<const float4*>(rp + 4 * t);
                vin[4 * t + 0] = q.x; vin[4 * t + 1] = q.y;
                vin[4 * t + 2] = q.z; vin[4 * t + 3] = q.w;
            }
            #pragma unroll
            for (int kx = 0; kx < K; kx++)
                #pragma unroll
                for (int j = 0; j < RX; j++)
                    acc[i][j] = fmaf(wrow[kx], vin[kx + j], acc[i][j]);
        }
    }

    // ---- store: two float4 per row per thread ----
    float* obase = out + (size_t)(b * CC + ch) * HH * WW;
    #pragma unroll
    for (int i = 0; i < RY; i++) {
        float* op = &obase[(size_t)(tileY0 + r0 + 2 * i) * WW + tileX0 + c0];
        float4 v0, v1;
        v0.x = acc[i][0]; v0.y = acc[i][1]; v0.z = acc[i][2]; v0.w = acc[i][3];
        v1.x = acc[i][4]; v1.y = acc[i][5]; v1.z = acc[i][6]; v1.w = acc[i][7];
        *reinterpret_cast<float4*>(op)     = v0;
        *reinterpret_cast<float4*>(op + 4) = v1;
    }
}

__global__ __launch_bounds__(NTH, 2)
void jagged_conv(const float* __restrict__ x,
                 const float* __restrict__ kern,
                 float* __restrict__ out)
{
    extern __shared__ float smem[];
    const int z  = blockIdx.z;
    const int ch = (CC - 1) - (z >> 2);   // descending K: big kernels first
    const int b  = z & 3;

    // k_i = floor(5 + 24*i/127), forced odd (matches np.linspace/astype)
    int k = 5 + (24 * ch) / 127;
    if ((k & 1) == 0) k -= 1;

    switch (k) {
        case  5: conv_body< 5>(x, kern, out, ch, b, smem); break;
        case  7: conv_body< 7>(x, kern, out, ch, b, smem); break;
        case  9: conv_body< 9>(x, kern, out, ch, b, smem); break;
        case 11: conv_body<11>(x, kern, out, ch, b, smem); break;
        case 13: conv_body<13>(x, kern, out, ch, b, smem); break;
        case 15: conv_body<15>(x, kern, out, ch, b, smem); break;
        case 17: conv_body<17>(x, kern, out, ch, b, smem); break;
        case 19: conv_body<19>(x, kern, out, ch, b, smem); break;
        case 21: conv_body<21>(x, kern, out, ch, b, smem); break;
        case 23: conv_body<23>(x, kern, out, ch, b, smem); break;
        case 25: conv_body<25>(x, kern, out, ch, b, smem); break;
        case 27: conv_body<27>(x, kern, out, ch, b, smem); break;
        case 29: conv_body<29>(x, kern, out, ch, b, smem); break;
        default: break;
    }
}

extern "C" void kernel_launch(void* const* d_in, const int* in_sizes, int n_in,
                              void* d_out, int out_size)
{
    (void)in_sizes; (void)n_in; (void)out_size;
    const float* x    = (const float*)d_in[0];
    const float* kern = (const float*)d_in[1];
    float* out        = (float*)d_out;

    // smem sized for K=29: WT_OFF + (TH+28) * SW(29)=92 floats
    const int smem_bytes = (WT_OFF + (TH + 28) * 92) * (int)sizeof(float);
    cudaFuncSetAttribute(jagged_conv,
                         cudaFuncAttributeMaxDynamicSharedMemorySize, smem_bytes);

    dim3 grid(WW / TW, HH / TH, BB * CC);
    dim3 block(NTH, 1, 1);
    jagged_conv<<<grid, block, smem_bytes>>>(x, kern, out);
}